// round 14
// baseline (speedup 1.0000x reference)
#include <cuda_runtime.h>

// BoidPolicy: all-pairs boids on a unit torus, N=8192, out acc [N,2] f32.
//
// Pipeline (graph-capturable, allocation-free, 2 launches):
//  kS: fused spatial sort, 32 blocks x 256 thr, two epoch spin barriers:
//      ph1: 16x16 snake cells + smem-atomic ranks + per-block histograms
//      ph2: per-block redundant offsets + scatter into interleaved pos/vel records
//      ph3: precompute per-pair bboxes (center + half-extent) -> g_bbox
//  k1: TWO blocks per 32-i tile (512 thr). Parity block culls its interleaved
//      half of the pairs using g_bbox (1 float4 + ~8 ops per pair), compacts
//      perception + separation lists, 16 warps take contiguous segments
//      (unroll-4, packed index loads), reduce, parity-ticketed fused epilogue.

#define NB      8192
#define NPAIR   (NB / 2)
#define NCELL   256
#define NBLKA   32
#define NTILE   256
#define TPB1    512
#define NWARP   16            // warps per block

#define SEP2F   4e-4f
#define PERC2F  0.04f
#define EPSF    1e-8f
#define MAGIC   12582912.0f   // 1.5 * 2^23
#define FULLM   0xffffffffu

typedef unsigned long long u64;
typedef unsigned short u16;

__device__ float4 g_pv[NB];             // pair p: [2p]=(xA,xB,yA,yB), [2p+1]=(vxA,vxB,vyA,vyB)
__device__ float4 g_bbox[NPAIR];        // pair p: (cx, cy, hx, hy)
__device__ int    g_orig[NB];
__device__ int    g_cnt[NBLKA * NCELL];
__device__ float  g_part[2][7][NB];     // [parity][comp][sorted boid]
__device__ int    g_ticket[NTILE];      // +2 per run; parity selects last arrival
__device__ unsigned g_barc[2];          // monotonic epoch barriers for kS

__device__ __forceinline__ u64 pack2(float lo, float hi) {
    u64 r; asm("mov.b64 %0,{%1,%2};" : "=l"(r) : "f"(lo), "f"(hi)); return r;
}
__device__ __forceinline__ void unpack2(u64 v, float& lo, float& hi) {
    asm("mov.b64 {%0,%1},%2;" : "=f"(lo), "=f"(hi) : "l"(v));
}
__device__ __forceinline__ u64 f2add(u64 a, u64 b) {
    u64 d; asm("add.rn.f32x2 %0,%1,%2;" : "=l"(d) : "l"(a), "l"(b)); return d;
}
__device__ __forceinline__ u64 f2mul(u64 a, u64 b) {
    u64 d; asm("mul.rn.f32x2 %0,%1,%2;" : "=l"(d) : "l"(a), "l"(b)); return d;
}
__device__ __forceinline__ u64 f2fma(u64 a, u64 b, u64 c) {
    u64 d; asm("fma.rn.f32x2 %0,%1,%2,%3;" : "=l"(d) : "l"(a), "l"(b), "l"(c)); return d;
}
// per-half: (t >= 0) ? 1.0f : 0.0f  (exact: copysign(0.5,t)+0.5)
__device__ __forceinline__ u64 f2mask(u64 t, u64 half2) {
    u64 s = (t & 0x8000000080000000ULL) | 0x3F0000003F000000ULL;
    return f2add(s, half2);
}
__device__ __forceinline__ float wrap1(float d) { return d - rintf(d); }
__device__ __forceinline__ float getX(const float* P, int idx) {
    return P[(idx >> 1) * 8 + (idx & 1)];
}
__device__ __forceinline__ float getY(const float* P, int idx) {
    return P[(idx >> 1) * 8 + 2 + (idx & 1)];
}

// epoch grid barrier for kS (32 co-resident blocks; counters monotonic -> replay-safe)
__device__ __forceinline__ void grid_barrier(int which, int tid) {
    __syncthreads();
    if (tid == 0) {
        __threadfence();
        const unsigned t = atomicAdd(&g_barc[which], 1u);
        const unsigned target = (t / NBLKA + 1u) * NBLKA;
        while (*((volatile unsigned*)&g_barc[which]) < target) { }
    }
    __syncthreads();
}

// ---------------- kS: fused sort + bbox precompute ----------------
__global__ __launch_bounds__(256)
void kS_sort(const float2* __restrict__ pos, const float2* __restrict__ vel)
{
    __shared__ int hist[NCELL];
    __shared__ int s_off[NCELL];
    __shared__ int wsum[8];
    __shared__ int wbase[8];

    const int tid  = threadIdx.x;
    const int lane = tid & 31;
    const int w    = tid >> 5;
    const int b    = blockIdx.x;

    // ---- phase 1: cells + ranks + histogram ----
    hist[tid] = 0;
    __syncthreads();

    const int e = b * 256 + tid;
    const float2 p = pos[e];
    int cx = (int)(p.x * 16.0f); cx = cx < 0 ? 0 : (cx > 15 ? 15 : cx);
    int cy = (int)(p.y * 16.0f); cy = cy < 0 ? 0 : (cy > 15 ? 15 : cy);
    const int lx   = (cy & 1) ? (15 - cx) : cx;       // snake order
    const int cell = (cy << 4) | lx;
    const int rank = atomicAdd(&hist[cell], 1);
    __syncthreads();
    g_cnt[b * NCELL + tid] = hist[tid];

    grid_barrier(0, tid);

    // ---- phase 2: per-block redundant offsets + scatter ----
    int tot = 0, part = 0;
    #pragma unroll
    for (int g = 0; g < NBLKA; ++g) {
        const int v = g_cnt[g * NCELL + tid];
        tot += v;
        if (g < b) part += v;
    }
    int s = tot;
    #pragma unroll
    for (int o = 1; o < 32; o <<= 1) {
        const int t = __shfl_up_sync(FULLM, s, o);
        if (lane >= o) s += t;
    }
    if (lane == 31) wsum[w] = s;
    __syncthreads();
    if (tid == 0) {
        int acc = 0;
        #pragma unroll
        for (int k = 0; k < 8; ++k) { wbase[k] = acc; acc += wsum[k]; }
    }
    __syncthreads();
    s_off[tid] = wbase[w] + s - tot + part;
    __syncthreads();

    const int dst = s_off[cell] + rank;
    const float2 v = vel[e];
    float* PV = (float*)g_pv;
    const int bb = (dst >> 1) * 8 + (dst & 1);
    PV[bb]     = p.x;
    PV[bb + 2] = p.y;
    PV[bb + 4] = v.x;
    PV[bb + 6] = v.y;
    g_orig[dst] = e;

    grid_barrier(1, tid);

    // ---- phase 3: pair bboxes (128 pairs per block) ----
    if (tid < 128) {
        const int pp = b * 128 + tid;
        const float4 r4 = g_pv[pp * 2];         // (xA, xB, yA, yB)
        const float pmnx = fminf(r4.x, r4.y), pmxx = fmaxf(r4.x, r4.y);
        const float pmny = fminf(r4.z, r4.w), pmxy = fmaxf(r4.z, r4.w);
        g_bbox[pp] = make_float4(0.5f * (pmnx + pmxx),
                                 0.5f * (pmny + pmxy),
                                 0.5f * (pmxx - pmnx),
                                 0.5f * (pmxy - pmny));
    }
}

// ---------------- k1: half-cull + compact + pair math + epilogue ----------------
#define PAIR_MAIN(PJ, VJ)                                                     \
    {                                                                         \
        const u64 dx2 = f2add((PJ).x, nxi2);                                  \
        const u64 rxp = f2add(f2add(dx2, C2), nC2);                           \
        const u64 dwx = f2fma(rxp, nOne2, dx2);                               \
        const u64 dy2 = f2add((PJ).y, nyi2);                                  \
        const u64 ryp = f2add(f2add(dy2, C2), nC2);                           \
        const u64 dwy = f2fma(ryp, nOne2, dy2);                               \
        const u64 d2  = f2fma(dwy, dwy, f2mul(dwx, dwx));                     \
        const u64 mp  = f2mask(f2fma(d2, nOne2, perc2c), half2);              \
        Px2 = f2fma(dwx, mp, Px2);                                            \
        Py2 = f2fma(dwy, mp, Py2);                                            \
        Vx2 = f2fma((VJ).x, mp, Vx2);                                         \
        Vy2 = f2fma((VJ).y, mp, Vy2);                                         \
        Cn2 = f2add(Cn2, mp);                                                 \
    }

__global__ __launch_bounds__(TPB1, 3)
void k1_main(const float2* __restrict__ vel,
             const float2* __restrict__ noise,
             const float*  __restrict__ w_sep,
             const float*  __restrict__ w_ali,
             const float*  __restrict__ w_coh,
             const float*  __restrict__ w_ns,
             float2*       __restrict__ out)
{
    __shared__ int      s_scanP[NWARP];
    __shared__ int      s_scanS[NWARP];
    __shared__ int      s_totalP, s_totalS, s_last;
    __shared__ __align__(8) u16 s_pairs[NB / 4];   // this block's half: 2048 max
    __shared__ u16      s_sep[NB / 4];
    __shared__ float    red[NWARP][32][8];

    const int tid    = threadIdx.x;
    const int lane   = tid & 31;
    const int w      = tid >> 5;
    const int g      = blockIdx.x >> 1;    // i-tile
    const int parity = blockIdx.x & 1;
    const int i      = g * 32 + lane;

    const float* P = (const float*)g_pv;
    const float pix = getX(P, i);
    const float piy = getY(P, i);

    // --- tile bbox (each warp computes an identical copy via shuffles) ---
    const float x0 = __shfl_sync(FULLM, pix, 0);
    const float y0 = __shfl_sync(FULLM, piy, 0);
    const float rx = wrap1(pix - x0);
    const float ry = wrap1(piy - y0);
    float mnx = rx, mxx = rx, mny = ry, mxy = ry;
    #pragma unroll
    for (int o = 16; o; o >>= 1) {
        mnx = fminf(mnx, __shfl_xor_sync(FULLM, mnx, o));
        mxx = fmaxf(mxx, __shfl_xor_sync(FULLM, mxx, o));
        mny = fminf(mny, __shfl_xor_sync(FULLM, mny, o));
        mxy = fmaxf(mxy, __shfl_xor_sync(FULLM, mxy, o));
    }
    const float bcx = x0 + 0.5f * (mnx + mxx);
    const float bcy = y0 + 0.5f * (mny + mxy);
    const float mrgx = 0.5f * (mxx - mnx) + 1e-5f;   // tile half-extent + slack
    const float mrgy = 0.5f * (mxy - mny) + 1e-5f;

    // --- pair-bbox liveness over THIS BLOCK'S interleaved half ---
    // m = tid*4 + q enumerates 2048 locals; p = (m>>3)<<4 | parity<<3 | (m&7).
    unsigned plP = 0, plS = 0;
    const int m0 = tid * 4;
    const int p0 = ((m0 >> 3) << 4) | (parity << 3) | (m0 & 7);
    #pragma unroll
    for (int q = 0; q < 4; ++q) {
        const float4 bb = g_bbox[p0 + q];       // (cx, cy, hx, hy)
        const float gx = fmaxf(0.0f, fabsf(wrap1(bcx - bb.x)) - mrgx - bb.z);
        const float gy = fmaxf(0.0f, fabsf(wrap1(bcy - bb.y)) - mrgy - bb.w);
        const float gap2 = gx * gx + gy * gy;
        plP |= (gap2 <= PERC2F ? 1u : 0u) << q;
        plS |= (gap2 <= SEP2F  ? 1u : 0u) << q;
    }

    const int cntP = __popc(plP);
    const int cntS = __popc(plS);
    int sP = cntP, sS = cntS;
    #pragma unroll
    for (int o = 1; o < 32; o <<= 1) {
        const int tP = __shfl_up_sync(FULLM, sP, o);
        const int tS = __shfl_up_sync(FULLM, sS, o);
        if (lane >= o) { sP += tP; sS += tS; }
    }
    if (lane == 31) { s_scanP[w] = sP; s_scanS[w] = sS; }
    __syncthreads();
    if (tid == 0) {
        int aP = 0, aS = 0;
        #pragma unroll
        for (int k = 0; k < NWARP; ++k) {
            const int vP = s_scanP[k]; s_scanP[k] = aP; aP += vP;
            const int vS = s_scanS[k]; s_scanS[k] = aS; aS += vS;
        }
        s_totalP = aP; s_totalS = aS;
    }
    __syncthreads();
    {
        int oP = s_scanP[w] + sP - cntP;
        unsigned m2 = plP;
        while (m2) { const int b = __ffs(m2) - 1; m2 &= m2 - 1; s_pairs[oP++] = (u16)(p0 + b); }
        int oS = s_scanS[w] + sS - cntS;
        m2 = plS;
        while (m2) { const int b = __ffs(m2) - 1; m2 &= m2 - 1; s_sep[oS++] = (u16)(p0 + b); }
    }
    __syncthreads();
    const int total    = s_totalP;
    const int sepTotal = s_totalS;

    // --- constants & accumulators ---
    const u64 nxi2   = pack2(-pix, -pix);
    const u64 nyi2   = pack2(-piy, -piy);
    const u64 C2     = pack2( MAGIC,  MAGIC);
    const u64 nC2    = pack2(-MAGIC, -MAGIC);
    const u64 nOne2  = pack2(-1.0f, -1.0f);
    const u64 half2  = pack2(0.5f, 0.5f);
    const u64 sep2c  = pack2(SEP2F, SEP2F);
    const u64 perc2c = pack2(PERC2F, PERC2F);

    u64 Sx2 = 0, Sy2 = 0, Px2 = 0, Py2 = 0, Vx2 = 0, Vy2 = 0, Cn2 = 0;

    const ulonglong2* __restrict__ PV2 = (const ulonglong2*)g_pv;

    // --- main loop: warp w takes contiguous segment of this block's list ---
    int k           = ((total * w) >> 4) & ~3;      // NWARP = 16
    const int kend4 = (w == 15) ? (total & ~3) : (((total * (w + 1)) >> 4) & ~3);

    for (; k < kend4; k += 4) {
        const uint2 pk = *(const uint2*)(s_pairs + k);
        const int i0 = pk.x & 0xffff;
        const int i1 = pk.x >> 16;
        const int i2 = pk.y & 0xffff;
        const int i3 = pk.y >> 16;
        const ulonglong2 pj0 = PV2[i0 * 2];
        const ulonglong2 vj0 = PV2[i0 * 2 + 1];
        const ulonglong2 pj1 = PV2[i1 * 2];
        const ulonglong2 vj1 = PV2[i1 * 2 + 1];
        const ulonglong2 pj2 = PV2[i2 * 2];
        const ulonglong2 vj2 = PV2[i2 * 2 + 1];
        const ulonglong2 pj3 = PV2[i3 * 2];
        const ulonglong2 vj3 = PV2[i3 * 2 + 1];
        PAIR_MAIN(pj0, vj0)
        PAIR_MAIN(pj1, vj1)
        PAIR_MAIN(pj2, vj2)
        PAIR_MAIN(pj3, vj3)
    }
    if (w == 15) {
        for (k = total & ~3; k < total; ++k) {
            const int i0 = s_pairs[k];
            const ulonglong2 pj0 = PV2[i0 * 2];
            const ulonglong2 vj0 = PV2[i0 * 2 + 1];
            PAIR_MAIN(pj0, vj0)
        }
    }

    // --- separation side loop (tiny: sep radius = 0.02) ---
    for (int ks = w; ks < sepTotal; ks += NWARP) {
        const int i0 = s_sep[ks];
        const ulonglong2 pj = PV2[i0 * 2];
        const u64 dx2 = f2add(pj.x, nxi2);
        const u64 rxp = f2add(f2add(dx2, C2), nC2);
        const u64 dwx = f2fma(rxp, nOne2, dx2);
        const u64 dy2 = f2add(pj.y, nyi2);
        const u64 ryp = f2add(f2add(dy2, C2), nC2);
        const u64 dwy = f2fma(ryp, nOne2, dy2);
        const u64 d2  = f2fma(dwy, dwy, f2mul(dwx, dwx));
        const u64 ms  = f2mask(f2fma(d2, nOne2, sep2c), half2);
        Sx2 = f2fma(dwx, ms, Sx2);
        Sy2 = f2fma(dwy, ms, Sy2);
    }

    // --- smem reduce (deterministic within block) ---
    float a, b;
    unpack2(Sx2, a, b);  red[w][lane][0] = a + b;
    unpack2(Sy2, a, b);  red[w][lane][1] = a + b;
    unpack2(Px2, a, b);  red[w][lane][2] = a + b;
    unpack2(Py2, a, b);  red[w][lane][3] = a + b;
    unpack2(Vx2, a, b);  red[w][lane][4] = a + b;
    unpack2(Vy2, a, b);  red[w][lane][5] = a + b;
    unpack2(Cn2, a, b);  red[w][lane][6] = a + b;
    __syncthreads();

    float s7[7];
    if (tid < 32) {
        #pragma unroll
        for (int comp = 0; comp < 7; ++comp) {
            float acc = 0.0f;
            #pragma unroll
            for (int sg = 0; sg < NWARP; ++sg) acc += red[sg][tid][comp];
            s7[comp] = acc;
            g_part[parity][comp][g * 32 + tid] = acc;
        }
        __threadfence();
    }
    __syncthreads();
    if (tid == 0) {
        const int old = atomicAdd(&g_ticket[g], 1);
        s_last = (old & 1);                    // 2 arrivals per run; parity selects last
    }
    __syncthreads();

    if (s_last && tid < 32) {
        __threadfence();
        // combine: part0 + part1 (fp add commutative -> same value either way)
        #pragma unroll
        for (int comp = 0; comp < 7; ++comp)
            s7[comp] += g_part[1 - parity][comp][g * 32 + tid];

        const float Sx = s7[0], Sy = s7[1], Px = s7[2], Py = s7[3];
        const float Vx = s7[4], Vy = s7[5];
        const float C  = s7[6] - 1.0f;         // remove self

        const int orig = g_orig[g * 32 + tid];
        const float2 vi = vel[orig];
        const float2 nz = noise[orig];

        float nrm = sqrtf(Sx * Sx + Sy * Sy);
        float inv = 1.0f / fmaxf(nrm, EPSF);
        const float sepx = -Sx * inv;
        const float sepy = -Sy * inv;

        const float invC = 1.0f / C;

        const float avx = (Vx - vi.x) * invC - vi.x;
        const float avy = (Vy - vi.y) * invC - vi.y;
        nrm = sqrtf(avx * avx + avy * avy);
        inv = 1.0f / fmaxf(nrm, EPSF);
        const float alix = avx * inv;
        const float aliy = avy * inv;

        const float cx2 = Px * invC;
        const float cy2 = Py * invC;
        nrm = sqrtf(cx2 * cx2 + cy2 * cy2);
        inv = 1.0f / fmaxf(nrm, EPSF);
        const float cohx = cx2 * inv;
        const float cohy = cy2 * inv;

        const float ws = *w_sep;
        const float wa = *w_ali;
        const float wc = *w_coh;
        const float wn = *w_ns;

        float ax = ws * sepx + wa * alix + wc * cohx + wn * nz.x;
        float ay = ws * sepy + wa * aliy + wc * cohy + wn * nz.y;

        nrm = sqrtf(ax * ax + ay * ay);
        if (nrm > 1.0f) {
            const float sc = 1.0f / fmaxf(nrm, EPSF);
            ax *= sc;
            ay *= sc;
        }

        out[orig] = make_float2(ax, ay);
    }
}

extern "C" void kernel_launch(void* const* d_in, const int* in_sizes, int n_in,
                              void* d_out, int out_size)
{
    const float2* pos   = (const float2*)d_in[0];
    const float2* vel   = (const float2*)d_in[1];
    const float2* noise = (const float2*)d_in[2];
    const float*  wsep  = (const float*)d_in[3];
    const float*  wali  = (const float*)d_in[4];
    const float*  wcoh  = (const float*)d_in[5];
    const float*  wns   = (const float*)d_in[6];
    float2* out = (float2*)d_out;

    kS_sort<<<NBLKA, 256>>>(pos, vel);
    k1_main<<<NTILE * 2, TPB1>>>(vel, noise, wsep, wali, wcoh, wns, out);
}

// round 15
// speedup vs baseline: 1.1985x; 1.1985x over previous
#include <cuda_runtime.h>

// BoidPolicy: all-pairs boids on a unit torus, N=8192, out acc [N,2] f32.
//
// Pipeline (graph-capturable, allocation-free, 2 launches):
//  kS: fused spatial sort, 32 blocks x 256 thr, two epoch spin barriers:
//      ph1: 16x16 snake cells + smem-atomic ranks + per-block histograms
//      ph2: per-block redundant offsets + scatter into interleaved pos/vel records
//      ph3: precompute per-pair bboxes (center + half-extent) -> g_bbox
//  k1: TWO blocks per 32-i tile (512 thr). Parity block culls its interleaved
//      half of the pairs via g_bbox, compacts perception + separation index
//      lists, STAGES live pair data into contiguous smem pre-translated into
//      the tile frame (wrap folded in), main loop = sequential smem + frame
//      math (no gathers, no wrap ops), reduce, parity-ticketed fused epilogue.

#define NB      8192
#define NPAIR   (NB / 2)
#define NCELL   256
#define NBLKA   32
#define NTILE   256
#define TPB1    512
#define NWARP   16            // warps per block
#define SCAP    1216          // staged live-pair capacity (overflow -> slow path)

#define SEP2F   4e-4f
#define PERC2F  0.04f
#define EPSF    1e-8f
#define MAGIC   12582912.0f   // 1.5 * 2^23
#define FULLM   0xffffffffu

typedef unsigned long long u64;
typedef unsigned short u16;

__device__ float4 g_pv[NB];             // pair p: [2p]=(xA,xB,yA,yB), [2p+1]=(vxA,vxB,vyA,vyB)
__device__ float4 g_bbox[NPAIR];        // pair p: (cx, cy, hx, hy)
__device__ int    g_orig[NB];
__device__ int    g_cnt[NBLKA * NCELL];
__device__ float  g_part[2][7][NB];     // [parity][comp][sorted boid]
__device__ int    g_ticket[NTILE];      // +2 per run; parity selects last arrival
__device__ unsigned g_barc[2];          // monotonic epoch barriers for kS

__device__ __forceinline__ u64 pack2(float lo, float hi) {
    u64 r; asm("mov.b64 %0,{%1,%2};" : "=l"(r) : "f"(lo), "f"(hi)); return r;
}
__device__ __forceinline__ void unpack2(u64 v, float& lo, float& hi) {
    asm("mov.b64 {%0,%1},%2;" : "=f"(lo), "=f"(hi) : "l"(v));
}
__device__ __forceinline__ u64 f2add(u64 a, u64 b) {
    u64 d; asm("add.rn.f32x2 %0,%1,%2;" : "=l"(d) : "l"(a), "l"(b)); return d;
}
__device__ __forceinline__ u64 f2mul(u64 a, u64 b) {
    u64 d; asm("mul.rn.f32x2 %0,%1,%2;" : "=l"(d) : "l"(a), "l"(b)); return d;
}
__device__ __forceinline__ u64 f2fma(u64 a, u64 b, u64 c) {
    u64 d; asm("fma.rn.f32x2 %0,%1,%2,%3;" : "=l"(d) : "l"(a), "l"(b), "l"(c)); return d;
}
// per-half: (t >= 0) ? 1.0f : 0.0f  (exact: copysign(0.5,t)+0.5)
__device__ __forceinline__ u64 f2mask(u64 t, u64 half2) {
    u64 s = (t & 0x8000000080000000ULL) | 0x3F0000003F000000ULL;
    return f2add(s, half2);
}
__device__ __forceinline__ float wrap1(float d) { return d - rintf(d); }
__device__ __forceinline__ float getX(const float* P, int idx) {
    return P[(idx >> 1) * 8 + (idx & 1)];
}
__device__ __forceinline__ float getY(const float* P, int idx) {
    return P[(idx >> 1) * 8 + 2 + (idx & 1)];
}

// epoch grid barrier for kS (32 co-resident blocks; counters monotonic -> replay-safe)
__device__ __forceinline__ void grid_barrier(int which, int tid) {
    __syncthreads();
    if (tid == 0) {
        __threadfence();
        const unsigned t = atomicAdd(&g_barc[which], 1u);
        const unsigned target = (t / NBLKA + 1u) * NBLKA;
        while (*((volatile unsigned*)&g_barc[which]) < target) { }
    }
    __syncthreads();
}

// ---------------- kS: fused sort + bbox precompute ----------------
__global__ __launch_bounds__(256)
void kS_sort(const float2* __restrict__ pos, const float2* __restrict__ vel)
{
    __shared__ int hist[NCELL];
    __shared__ int s_off[NCELL];
    __shared__ int wsum[8];
    __shared__ int wbase[8];

    const int tid  = threadIdx.x;
    const int lane = tid & 31;
    const int w    = tid >> 5;
    const int b    = blockIdx.x;

    // ---- phase 1: cells + ranks + histogram ----
    hist[tid] = 0;
    __syncthreads();

    const int e = b * 256 + tid;
    const float2 p = pos[e];
    int cx = (int)(p.x * 16.0f); cx = cx < 0 ? 0 : (cx > 15 ? 15 : cx);
    int cy = (int)(p.y * 16.0f); cy = cy < 0 ? 0 : (cy > 15 ? 15 : cy);
    const int lx   = (cy & 1) ? (15 - cx) : cx;       // snake order
    const int cell = (cy << 4) | lx;
    const int rank = atomicAdd(&hist[cell], 1);
    __syncthreads();
    g_cnt[b * NCELL + tid] = hist[tid];

    grid_barrier(0, tid);

    // ---- phase 2: per-block redundant offsets + scatter ----
    int tot = 0, part = 0;
    #pragma unroll
    for (int g = 0; g < NBLKA; ++g) {
        const int v = g_cnt[g * NCELL + tid];
        tot += v;
        if (g < b) part += v;
    }
    int s = tot;
    #pragma unroll
    for (int o = 1; o < 32; o <<= 1) {
        const int t = __shfl_up_sync(FULLM, s, o);
        if (lane >= o) s += t;
    }
    if (lane == 31) wsum[w] = s;
    __syncthreads();
    if (tid == 0) {
        int acc = 0;
        #pragma unroll
        for (int k = 0; k < 8; ++k) { wbase[k] = acc; acc += wsum[k]; }
    }
    __syncthreads();
    s_off[tid] = wbase[w] + s - tot + part;
    __syncthreads();

    const int dst = s_off[cell] + rank;
    const float2 v = vel[e];
    float* PV = (float*)g_pv;
    const int bb = (dst >> 1) * 8 + (dst & 1);
    PV[bb]     = p.x;
    PV[bb + 2] = p.y;
    PV[bb + 4] = v.x;
    PV[bb + 6] = v.y;
    g_orig[dst] = e;

    grid_barrier(1, tid);

    // ---- phase 3: pair bboxes (128 pairs per block) ----
    if (tid < 128) {
        const int pp = b * 128 + tid;
        const float4 r4 = g_pv[pp * 2];         // (xA, xB, yA, yB)
        const float pmnx = fminf(r4.x, r4.y), pmxx = fmaxf(r4.x, r4.y);
        const float pmny = fminf(r4.z, r4.w), pmxy = fmaxf(r4.z, r4.w);
        g_bbox[pp] = make_float4(0.5f * (pmnx + pmxx),
                                 0.5f * (pmny + pmxy),
                                 0.5f * (pmxx - pmnx),
                                 0.5f * (pmxy - pmny));
    }
}

// ---------------- k1 ----------------
// Frame-math body: pos/vel already tile-frame translated & packed.
#define PAIR_FRAME(PJ, VJ)                                                    \
    {                                                                         \
        const u64 dx2 = f2add((PJ).x, fnx2);                                  \
        const u64 dy2 = f2add((PJ).y, fny2);                                  \
        const u64 d2  = f2fma(dy2, dy2, f2mul(dx2, dx2));                     \
        const u64 mp  = f2mask(f2fma(d2, nOne2, perc2c), half2);              \
        Px2 = f2fma(dx2, mp, Px2);                                            \
        Py2 = f2fma(dy2, mp, Py2);                                            \
        Vx2 = f2fma((VJ).x, mp, Vx2);                                         \
        Vy2 = f2fma((VJ).y, mp, Vy2);                                         \
        Cn2 = f2add(Cn2, mp);                                                 \
    }

__global__ __launch_bounds__(TPB1, 3)
void k1_main(const float2* __restrict__ vel,
             const float2* __restrict__ noise,
             const float*  __restrict__ w_sep,
             const float*  __restrict__ w_ali,
             const float*  __restrict__ w_coh,
             const float*  __restrict__ w_ns,
             float2*       __restrict__ out)
{
    // one buffer, manual layout:
    //  [0, 4096)      s_pairs u16[2048]
    //  [4096, 8192)   s_sep   u16[2048]
    //  [8192, 27648)  s_spos  ulonglong2[SCAP]   (union with red after loops)
    //  [27648, 47104) s_svel  ulonglong2[SCAP]
    __shared__ __align__(16) char s_buf[8192 + SCAP * 32];
    __shared__ int s_scanP[NWARP];
    __shared__ int s_scanS[NWARP];
    __shared__ int s_totalP, s_totalS, s_last;

    u16*        s_pairs = (u16*)s_buf;
    u16*        s_sep   = (u16*)(s_buf + 4096);
    ulonglong2* s_spos  = (ulonglong2*)(s_buf + 8192);
    ulonglong2* s_svel  = (ulonglong2*)(s_buf + 8192 + SCAP * 16);
    float (*red)[32][8] = (float(*)[32][8])(s_buf + 8192);   // overlays stage

    const int tid    = threadIdx.x;
    const int lane   = tid & 31;
    const int w      = tid >> 5;
    const int g      = blockIdx.x >> 1;    // i-tile
    const int parity = blockIdx.x & 1;
    const int i      = g * 32 + lane;

    const float* P = (const float*)g_pv;
    const float pix = getX(P, i);
    const float piy = getY(P, i);

    // --- tile bbox + per-lane frame coords (each warp identical via shuffles) ---
    const float x0 = __shfl_sync(FULLM, pix, 0);
    const float y0 = __shfl_sync(FULLM, piy, 0);
    const float rx = wrap1(pix - x0);      // xi in tile frame
    const float ry = wrap1(piy - y0);
    float mnx = rx, mxx = rx, mny = ry, mxy = ry;
    #pragma unroll
    for (int o = 16; o; o >>= 1) {
        mnx = fminf(mnx, __shfl_xor_sync(FULLM, mnx, o));
        mxx = fmaxf(mxx, __shfl_xor_sync(FULLM, mxx, o));
        mny = fminf(mny, __shfl_xor_sync(FULLM, mny, o));
        mxy = fmaxf(mxy, __shfl_xor_sync(FULLM, mxy, o));
    }
    const float bcx = x0 + 0.5f * (mnx + mxx);
    const float bcy = y0 + 0.5f * (mny + mxy);
    const float mrgx = 0.5f * (mxx - mnx) + 1e-5f;
    const float mrgy = 0.5f * (mxy - mny) + 1e-5f;

    // --- pair-bbox liveness over THIS BLOCK'S interleaved half ---
    unsigned plP = 0, plS = 0;
    const int m0 = tid * 4;
    const int p0 = ((m0 >> 3) << 4) | (parity << 3) | (m0 & 7);
    #pragma unroll
    for (int q = 0; q < 4; ++q) {
        const float4 bb = g_bbox[p0 + q];
        const float gx = fmaxf(0.0f, fabsf(wrap1(bcx - bb.x)) - mrgx - bb.z);
        const float gy = fmaxf(0.0f, fabsf(wrap1(bcy - bb.y)) - mrgy - bb.w);
        const float gap2 = gx * gx + gy * gy;
        plP |= (gap2 <= PERC2F ? 1u : 0u) << q;
        plS |= (gap2 <= SEP2F  ? 1u : 0u) << q;
    }

    const int cntP = __popc(plP);
    const int cntS = __popc(plS);
    int sP = cntP, sS = cntS;
    #pragma unroll
    for (int o = 1; o < 32; o <<= 1) {
        const int tP = __shfl_up_sync(FULLM, sP, o);
        const int tS = __shfl_up_sync(FULLM, sS, o);
        if (lane >= o) { sP += tP; sS += tS; }
    }
    if (lane == 31) { s_scanP[w] = sP; s_scanS[w] = sS; }
    __syncthreads();
    if (tid == 0) {
        int aP = 0, aS = 0;
        #pragma unroll
        for (int k = 0; k < NWARP; ++k) {
            const int vP = s_scanP[k]; s_scanP[k] = aP; aP += vP;
            const int vS = s_scanS[k]; s_scanS[k] = aS; aS += vS;
        }
        s_totalP = aP; s_totalS = aS;
    }
    __syncthreads();
    {
        int oP = s_scanP[w] + sP - cntP;
        unsigned m2 = plP;
        while (m2) { const int b = __ffs(m2) - 1; m2 &= m2 - 1; s_pairs[oP++] = (u16)(p0 + b); }
        int oS = s_scanS[w] + sS - cntS;
        m2 = plS;
        while (m2) { const int b = __ffs(m2) - 1; m2 &= m2 - 1; s_sep[oS++] = (u16)(p0 + b); }
    }
    __syncthreads();
    const int total    = s_totalP;
    const int sepTotal = s_totalS;
    const int nstage   = total < SCAP ? total : SCAP;

    const ulonglong2* __restrict__ PV2 = (const ulonglong2*)g_pv;

    // --- staging: translate live pairs into the tile frame, pack into smem ---
    for (int e = tid; e < nstage; e += TPB1) {
        const int idx = s_pairs[e];
        const float4 r4 = g_pv[idx * 2];
        const ulonglong2 vv = PV2[idx * 2 + 1];
        const float xa = wrap1(r4.x - x0);
        const float xb = wrap1(r4.y - x0);
        const float ya = wrap1(r4.z - y0);
        const float yb = wrap1(r4.w - y0);
        ulonglong2 pp;
        pp.x = pack2(xa, xb);
        pp.y = pack2(ya, yb);
        s_spos[e] = pp;
        s_svel[e] = vv;
    }
    __syncthreads();

    // --- constants & accumulators (frame) ---
    const u64 fnx2   = pack2(-rx, -rx);
    const u64 fny2   = pack2(-ry, -ry);
    const u64 nOne2  = pack2(-1.0f, -1.0f);
    const u64 half2  = pack2(0.5f, 0.5f);
    const u64 sep2c  = pack2(SEP2F, SEP2F);
    const u64 perc2c = pack2(PERC2F, PERC2F);

    u64 Sx2 = 0, Sy2 = 0, Px2 = 0, Py2 = 0, Vx2 = 0, Vy2 = 0, Cn2 = 0;

    // --- main loop: warp w takes contiguous segment of staged data ---
    int k           = ((nstage * w) >> 4) & ~3;      // NWARP = 16
    const int kend4 = (w == 15) ? (nstage & ~3) : (((nstage * (w + 1)) >> 4) & ~3);

    for (; k < kend4; k += 4) {
        const ulonglong2 pj0 = s_spos[k + 0];
        const ulonglong2 pj1 = s_spos[k + 1];
        const ulonglong2 pj2 = s_spos[k + 2];
        const ulonglong2 pj3 = s_spos[k + 3];
        const ulonglong2 vj0 = s_svel[k + 0];
        const ulonglong2 vj1 = s_svel[k + 1];
        const ulonglong2 vj2 = s_svel[k + 2];
        const ulonglong2 vj3 = s_svel[k + 3];
        PAIR_FRAME(pj0, vj0)
        PAIR_FRAME(pj1, vj1)
        PAIR_FRAME(pj2, vj2)
        PAIR_FRAME(pj3, vj3)
    }
    if (w == 15) {
        for (k = nstage & ~3; k < nstage; ++k) {
            const ulonglong2 pj0 = s_spos[k];
            const ulonglong2 vj0 = s_svel[k];
            PAIR_FRAME(pj0, vj0)
        }
    }
    // overflow (total > SCAP; never in practice, correct if ever): on-the-fly transform
    for (int ko = SCAP + w; ko < total; ko += NWARP) {
        const int idx = s_pairs[ko];
        const float4 r4 = g_pv[idx * 2];
        const ulonglong2 vv = PV2[idx * 2 + 1];
        ulonglong2 pp;
        pp.x = pack2(wrap1(r4.x - x0), wrap1(r4.y - x0));
        pp.y = pack2(wrap1(r4.z - y0), wrap1(r4.w - y0));
        PAIR_FRAME(pp, vv)
    }

    // --- separation side loop (tiny; frame transform on the fly) ---
    for (int ks = w; ks < sepTotal; ks += NWARP) {
        const int idx = s_sep[ks];
        const float4 r4 = g_pv[idx * 2];
        ulonglong2 pp;
        pp.x = pack2(wrap1(r4.x - x0), wrap1(r4.y - x0));
        pp.y = pack2(wrap1(r4.z - y0), wrap1(r4.w - y0));
        const u64 dx2 = f2add(pp.x, fnx2);
        const u64 dy2 = f2add(pp.y, fny2);
        const u64 d2  = f2fma(dy2, dy2, f2mul(dx2, dx2));
        const u64 ms  = f2mask(f2fma(d2, nOne2, sep2c), half2);
        Sx2 = f2fma(dx2, ms, Sx2);
        Sy2 = f2fma(dy2, ms, Sy2);
    }

    // --- retire staged data, then reduce (red overlays stage region) ---
    __syncthreads();
    float a, b;
    unpack2(Sx2, a, b);  red[w][lane][0] = a + b;
    unpack2(Sy2, a, b);  red[w][lane][1] = a + b;
    unpack2(Px2, a, b);  red[w][lane][2] = a + b;
    unpack2(Py2, a, b);  red[w][lane][3] = a + b;
    unpack2(Vx2, a, b);  red[w][lane][4] = a + b;
    unpack2(Vy2, a, b);  red[w][lane][5] = a + b;
    unpack2(Cn2, a, b);  red[w][lane][6] = a + b;
    __syncthreads();

    float s7[7];
    if (tid < 32) {
        #pragma unroll
        for (int comp = 0; comp < 7; ++comp) {
            float acc = 0.0f;
            #pragma unroll
            for (int sg = 0; sg < NWARP; ++sg) acc += red[sg][tid][comp];
            s7[comp] = acc;
            g_part[parity][comp][g * 32 + tid] = acc;
        }
        __threadfence();
    }
    __syncthreads();
    if (tid == 0) {
        const int old = atomicAdd(&g_ticket[g], 1);
        s_last = (old & 1);                    // 2 arrivals per run; parity selects last
    }
    __syncthreads();

    if (s_last && tid < 32) {
        __threadfence();
        #pragma unroll
        for (int comp = 0; comp < 7; ++comp)
            s7[comp] += g_part[1 - parity][comp][g * 32 + tid];

        const float Sx = s7[0], Sy = s7[1], Px = s7[2], Py = s7[3];
        const float Vx = s7[4], Vy = s7[5];
        const float C  = s7[6] - 1.0f;         // remove self

        const int orig = g_orig[g * 32 + tid];
        const float2 vi = vel[orig];
        const float2 nz = noise[orig];

        float nrm = sqrtf(Sx * Sx + Sy * Sy);
        float inv = 1.0f / fmaxf(nrm, EPSF);
        const float sepx = -Sx * inv;
        const float sepy = -Sy * inv;

        const float invC = 1.0f / C;

        const float avx = (Vx - vi.x) * invC - vi.x;
        const float avy = (Vy - vi.y) * invC - vi.y;
        nrm = sqrtf(avx * avx + avy * avy);
        inv = 1.0f / fmaxf(nrm, EPSF);
        const float alix = avx * inv;
        const float aliy = avy * inv;

        const float cx2 = Px * invC;
        const float cy2 = Py * invC;
        nrm = sqrtf(cx2 * cx2 + cy2 * cy2);
        inv = 1.0f / fmaxf(nrm, EPSF);
        const float cohx = cx2 * inv;
        const float cohy = cy2 * inv;

        const float ws = *w_sep;
        const float wa = *w_ali;
        const float wc = *w_coh;
        const float wn = *w_ns;

        float ax = ws * sepx + wa * alix + wc * cohx + wn * nz.x;
        float ay = ws * sepy + wa * aliy + wc * cohy + wn * nz.y;

        nrm = sqrtf(ax * ax + ay * ay);
        if (nrm > 1.0f) {
            const float sc = 1.0f / fmaxf(nrm, EPSF);
            ax *= sc;
            ay *= sc;
        }

        out[orig] = make_float2(ax, ay);
    }
}

extern "C" void kernel_launch(void* const* d_in, const int* in_sizes, int n_in,
                              void* d_out, int out_size)
{
    const float2* pos   = (const float2*)d_in[0];
    const float2* vel   = (const float2*)d_in[1];
    const float2* noise = (const float2*)d_in[2];
    const float*  wsep  = (const float*)d_in[3];
    const float*  wali  = (const float*)d_in[4];
    const float*  wcoh  = (const float*)d_in[5];
    const float*  wns   = (const float*)d_in[6];
    float2* out = (float2*)d_out;

    kS_sort<<<NBLKA, 256>>>(pos, vel);
    k1_main<<<NTILE * 2, TPB1>>>(vel, noise, wsep, wali, wcoh, wns, out);
}